// round 17
// baseline (speedup 1.0000x reference)
#include <cuda_runtime.h>
#include <cstdint>
#include <cstddef>

// ---------------------------------------------------------------------------
// MIDIMultiInstanceAttention  (B=8, N=512, D=1024, H=16, HD=64, NI=4)
// tf32 tensor cores; ldmatrix fragments; fixed-bound softmax; transposed
// weights; rank-5 gate; 64x64 warp tiles in GEMMs (4 warps/block)
// ---------------------------------------------------------------------------

#define CB 8
#define CN 512
#define CD 1024
#define CH 16
#define CHD 64
#define CM 4096
#define ATT_SCALE 0.125f
#define SOFT_SHIFT 8.0f
#define INST_SCALE (0.125f / 16.0f)

#define APAD 36
#define KPAD 68
#define PPAD 68

#define GA_AW (128 * APAD)                 // 4608 words
#define GA_STAGE (2 * GA_AW)               // A + B(t), 9216 words
#define SMEM_GEMM (2 * GA_STAGE * 4)       // 73728 B

#define AT_KV (64 * KPAD)                  // 4352 words
#define AT_STAGE (2 * AT_KV)               // K + Vt
#define SMEM_ATTN ((2 * AT_STAGE + 4 * 32 * PPAD) * 4)   // 104448 B

// scratch (device globals: allocation-free rule)
__device__ __align__(16) uint32_t g_xt[CM * CD];
__device__ __align__(16) uint32_t g_wq[CD * CD];    // transposed tf32 [n][k]
__device__ __align__(16) uint32_t g_wk[CD * CD];
__device__ __align__(16) uint32_t g_wv[CD * CD];
__device__ __align__(16) uint32_t g_wo[CD * CD];
__device__ __align__(16) float g_q [CM * CD];       // tf32 bits (pre-scaled)
__device__ __align__(16) float g_k [CM * CD];       // tf32 bits
__device__ __align__(16) float g_vt[CM * CD];       // tf32 bits, [b,h][d][n]
__device__ __align__(16) float g_o [CM * CD];       // tf32 bits
__device__ __align__(16) float g_e2[4 * CD];        // emb[:4] @ Wik
__device__ __align__(16) float g_m [1025 * 8];      // rows 0..1023: [M(4), mv, pad]; row 1024: biq-row
__device__ __align__(16) float g_ug[CM * 8];        // per token: U0..U3, w, pad
__device__ float g_gacc[CM];

__global__ void zero_e2_k() {
    int i = blockIdx.x * 256 + threadIdx.x;
    if (i < 4 * CD) g_e2[i] = 0.0f;
}

// ---------------------------------------------------------------------------
// helpers
// ---------------------------------------------------------------------------
__device__ __forceinline__ uint32_t f2tf32(float x) {
    uint32_t r;
    asm("cvt.rna.tf32.f32 %0, %1;" : "=r"(r) : "f"(x));
    return r;
}

__device__ __forceinline__ void mma_tf32(float* d, const uint32_t* a, const uint32_t* b) {
    asm volatile(
        "mma.sync.aligned.m16n8k8.row.col.f32.tf32.tf32.f32 "
        "{%0,%1,%2,%3}, {%4,%5,%6,%7}, {%8,%9}, {%0,%1,%2,%3};\n"
        : "+f"(d[0]), "+f"(d[1]), "+f"(d[2]), "+f"(d[3])
        : "r"(a[0]), "r"(a[1]), "r"(a[2]), "r"(a[3]), "r"(b[0]), "r"(b[1]));
}

__device__ __forceinline__ void ldsm_x4(uint32_t* r, uint32_t saddr) {
    asm volatile("ldmatrix.sync.aligned.m8n8.x4.shared.b16 {%0,%1,%2,%3}, [%4];\n"
        : "=r"(r[0]), "=r"(r[1]), "=r"(r[2]), "=r"(r[3]) : "r"(saddr));
}

__device__ __forceinline__ void cp16(uint32_t dst, const void* src) {
    asm volatile("cp.async.cg.shared.global [%0], [%1], 16;\n" :: "r"(dst), "l"(src));
}
#define CP_COMMIT() asm volatile("cp.async.commit_group;\n")
#define CP_WAIT0()  asm volatile("cp.async.wait_group 0;\n")

// x -> tf32 bits (no transpose)
__global__ void cvt_x_k(const float* __restrict__ x, uint32_t* __restrict__ xt) {
    int i = blockIdx.x * 256 + threadIdx.x;
    float4 v = ((const float4*)x)[i];
    uint4 o = {f2tf32(v.x), f2tf32(v.y), f2tf32(v.z), f2tf32(v.w)};
    ((uint4*)xt)[i] = o;
}

// 4 weights: cvt to tf32 bits AND transpose -> Wt[n][k]
__global__ void wtr_k(const float* __restrict__ w0, const float* __restrict__ w1,
                      const float* __restrict__ w2, const float* __restrict__ w3,
                      uint32_t* __restrict__ o0, uint32_t* __restrict__ o1,
                      uint32_t* __restrict__ o2, uint32_t* __restrict__ o3)
{
    __shared__ uint32_t ts[32][33];
    const int z = blockIdx.z;
    const float* src = (z == 0) ? w0 : (z == 1) ? w1 : (z == 2) ? w2 : w3;
    uint32_t*    dst = (z == 0) ? o0 : (z == 1) ? o1 : (z == 2) ? o2 : o3;
    const int n0 = blockIdx.x * 32;
    const int k0 = blockIdx.y * 32;
    const int c  = threadIdx.x & 31;
    const int r8 = threadIdx.x >> 5;
#pragma unroll
    for (int i = 0; i < 4; i++) {
        int r = r8 + i * 8;
        ts[r][c] = f2tf32(src[(size_t)(k0 + r) * CD + n0 + c]);
    }
    __syncthreads();
#pragma unroll
    for (int i = 0; i < 4; i++) {
        int r = r8 + i * 8;
        dst[(size_t)(n0 + r) * CD + k0 + c] = ts[c][r];
    }
}

// ---------------------------------------------------------------------------
// E2 = emb[:4] @ Wik, k-split 32 ways with atomic accumulation
// ---------------------------------------------------------------------------
__global__ void e2_k(const float* __restrict__ emb, const float* __restrict__ Wik) {
    int idx = blockIdx.x * 256 + threadIdx.x;
    int out = idx & 4095;
    int kc  = idx >> 12;
    int i = out >> 10;
    int c = out & 1023;
    const float* ep = emb + i * 1024 + kc * 32;
    const float* wp = Wik + (size_t)(kc * 32) * 1024 + c;
    float acc = 0.0f;
#pragma unroll
    for (int kk = 0; kk < 32; kk++)
        acc = fmaf(ep[kk], wp[(size_t)kk * 1024], acc);
    atomicAdd(&g_e2[out], acc);
}

// ---------------------------------------------------------------------------
// prep: g_m[k][i<4] = Wiq[k,:]·E2[i,:],  g_m[k][4] = Wiq[k,:]·bik
// row 1024 uses biq. one warp per row.
// ---------------------------------------------------------------------------
__global__ void prep_k(const float* __restrict__ Wiq, const float* __restrict__ biq,
                       const float* __restrict__ bik) {
    int w    = blockIdx.x * 8 + (threadIdx.x >> 5);
    int lane = threadIdx.x & 31;
    if (w > 1024) return;
    const float* row = (w < 1024) ? (Wiq + (size_t)w * CD) : biq;
    float a0 = 0.0f, a1 = 0.0f, a2 = 0.0f, a3 = 0.0f, a4 = 0.0f;
    for (int d = lane; d < CD; d += 32) {
        float r = row[d];
        a0 = fmaf(r, g_e2[d],        a0);
        a1 = fmaf(r, g_e2[1024 + d], a1);
        a2 = fmaf(r, g_e2[2048 + d], a2);
        a3 = fmaf(r, g_e2[3072 + d], a3);
        a4 = fmaf(r, bik[d],         a4);
    }
#pragma unroll
    for (int off = 16; off; off >>= 1) {
        a0 += __shfl_xor_sync(0xffffffffu, a0, off);
        a1 += __shfl_xor_sync(0xffffffffu, a1, off);
        a2 += __shfl_xor_sync(0xffffffffu, a2, off);
        a3 += __shfl_xor_sync(0xffffffffu, a3, off);
        a4 += __shfl_xor_sync(0xffffffffu, a4, off);
    }
    if (lane == 0) {
        float* mp = g_m + w * 8;
        mp[0] = a0; mp[1] = a1; mp[2] = a2; mp[3] = a3; mp[4] = a4;
    }
}

// ---------------------------------------------------------------------------
// uvw: per token n: U[n][i] = o[n,:]·M[:,i] + u0[i] (i<4), w = o[n,:]·mv + w0
// ---------------------------------------------------------------------------
__global__ void uvw_k(const float* __restrict__ o) {
    int n    = blockIdx.x * 8 + (threadIdx.x >> 5);
    int lane = threadIdx.x & 31;
    const float* op = o + (size_t)n * CD;
    float a0 = 0.0f, a1 = 0.0f, a2 = 0.0f, a3 = 0.0f, a4 = 0.0f;
    for (int d = lane; d < CD; d += 32) {
        float ov = op[d];
        const float* mp = g_m + d * 8;
        float4 m4 = *(const float4*)mp;
        a0 = fmaf(ov, m4.x, a0);
        a1 = fmaf(ov, m4.y, a1);
        a2 = fmaf(ov, m4.z, a2);
        a3 = fmaf(ov, m4.w, a3);
        a4 = fmaf(ov, mp[4], a4);
    }
#pragma unroll
    for (int off = 16; off; off >>= 1) {
        a0 += __shfl_xor_sync(0xffffffffu, a0, off);
        a1 += __shfl_xor_sync(0xffffffffu, a1, off);
        a2 += __shfl_xor_sync(0xffffffffu, a2, off);
        a3 += __shfl_xor_sync(0xffffffffu, a3, off);
        a4 += __shfl_xor_sync(0xffffffffu, a4, off);
    }
    if (lane == 0) {
        const float* u0 = g_m + 1024 * 8;
        float* up = g_ug + n * 8;
        up[0] = a0 + u0[0];
        up[1] = a1 + u0[1];
        up[2] = a2 + u0[2];
        up[3] = a3 + u0[3];
        up[4] = a4 + u0[4];
    }
}

// ---------------------------------------------------------------------------
// gate: gacc[b,n] = sum_m sigmoid((U[n]·mask[b,m] + w[n]) * INST_SCALE)
// ---------------------------------------------------------------------------
__global__ void gate_k(const float* __restrict__ mask) {
    int n    = blockIdx.x * 8 + (threadIdx.x >> 5);
    int lane = threadIdx.x & 31;
    int b    = n >> 9;
    const float* up = g_ug + n * 8;
    float u0 = up[0], u1 = up[1], u2 = up[2], u3 = up[3], wv = up[4];
    const float4* mp = (const float4*)(mask + (size_t)b * CN * 4);
    float acc = 0.0f;
#pragma unroll 4
    for (int m = lane; m < CN; m += 32) {
        float4 mk = mp[m];
        float s = wv;
        s = fmaf(u0, mk.x, s);
        s = fmaf(u1, mk.y, s);
        s = fmaf(u2, mk.z, s);
        s = fmaf(u3, mk.w, s);
        acc += 1.0f / (1.0f + __expf(-s * INST_SCALE));
    }
#pragma unroll
    for (int off = 16; off; off >>= 1)
        acc += __shfl_xor_sync(0xffffffffu, acc, off);
    if (lane == 0) g_gacc[n] = acc;
}

// ---------------------------------------------------------------------------
// fused QKV projection, 4 warps x 64x64 warp tiles.
// z selects {Wq,Wk,Wv} (transposed). z<2 -> fused per-head RMSNorm (a warp's
// 64 cols == exactly one head -> pure quad-shuffle reduction).
// z==2 -> V stored transposed.
// ---------------------------------------------------------------------------
__global__ __launch_bounds__(128, 2) void gemm_qkv(
    const uint32_t* __restrict__ A,
    const uint32_t* __restrict__ Wq_, const uint32_t* __restrict__ Wk_,
    const uint32_t* __restrict__ Wv_,
    const float* __restrict__ bq_, const float* __restrict__ bk_,
    const float* __restrict__ bv_,
    const float* __restrict__ qw_, const float* __restrict__ kw_,
    float* __restrict__ oq_, float* __restrict__ ok_, float* __restrict__ ov_)
{
    extern __shared__ uint32_t sm[];
    const int z = blockIdx.z;
    const uint32_t* W   = (z == 0) ? Wq_ : (z == 1) ? Wk_ : Wv_;
    const float* bias   = (z == 0) ? bq_ : (z == 1) ? bk_ : bv_;
    const float* normw  = (z == 0) ? qw_ : kw_;
    float* C            = (z == 0) ? oq_ : (z == 1) ? ok_ : ov_;
    const float qsc     = (z == 0) ? ATT_SCALE : 1.0f;

    const int tid  = threadIdx.x;
    const int lane = tid & 31;
    const int warp = tid >> 5;          // 0..3
    const int wm   = warp >> 1;         // 0..1 (64 rows)
    const int wn   = warp & 1;          // 0..1 (64 cols = one head)
    const int bm   = blockIdx.y * 128;
    const int bn   = blockIdx.x * 128;
    const int g    = lane >> 2;
    const int t    = lane & 3;
    const int lrow = lane & 7;
    const int lmat = lane >> 3;
    const uint32_t sb = (uint32_t)__cvta_generic_to_shared(sm);
    const int a_loff = ((lmat & 1) * 8 + lrow) * APAD + (lmat >> 1) * 4;
    const int b_loff = ((lmat >> 1) * 8 + lrow) * APAD + (lmat & 1) * 4;

    float acc[4][8][4];
#pragma unroll
    for (int i = 0; i < 4; i++)
#pragma unroll
        for (int j = 0; j < 8; j++)
#pragma unroll
            for (int r = 0; r < 4; r++) acc[i][j][r] = 0.0f;

    auto load_stage = [&](int kt, int st) {
        uint32_t as = sb + (uint32_t)(st * GA_STAGE) * 4u;
        uint32_t bs = as + GA_AW * 4u;
#pragma unroll
        for (int p = 0; p < 8; p++) {
            int idx = p * 128 + tid;
            int r = idx >> 3, c4 = (idx & 7) << 2;
            cp16(as + (uint32_t)(r * APAD + c4) * 4u,
                 A + (size_t)(bm + r) * CD + kt + c4);
            cp16(bs + (uint32_t)(r * APAD + c4) * 4u,
                 W + (size_t)(bn + r) * CD + kt + c4);
        }
        CP_COMMIT();
    };

    load_stage(0, 0);
    int st = 0;
    for (int it = 0; it < 32; it++) {
        CP_WAIT0();
        __syncthreads();
        if (it < 31) load_stage((it + 1) * 32, st ^ 1);
        const uint32_t as_b = sb + (uint32_t)(st * GA_STAGE) * 4u;
        const uint32_t bs_b = as_b + GA_AW * 4u;
#pragma unroll
        for (int ks = 0; ks < 4; ks++) {
            const int kc = ks * 8;
            uint32_t af[4][4], bq4[4][4];
#pragma unroll
            for (int mt = 0; mt < 4; mt++)
                ldsm_x4(af[mt], as_b + (uint32_t)((wm * 64 + mt * 16) * APAD + kc + a_loff) * 4u);
#pragma unroll
            for (int h2 = 0; h2 < 4; h2++)
                ldsm_x4(bq4[h2], bs_b + (uint32_t)((wn * 64 + h2 * 16) * APAD + kc + b_loff) * 4u);
#pragma unroll
            for (int mt = 0; mt < 4; mt++)
#pragma unroll
                for (int nt = 0; nt < 8; nt++)
                    mma_tf32(acc[mt][nt], af[mt], &bq4[nt >> 1][(nt & 1) * 2]);
        }
        st ^= 1;
    }

    float2 bb[8];
#pragma unroll
    for (int nt = 0; nt < 8; nt++)
        bb[nt] = *(const float2*)(bias + bn + wn * 64 + nt * 8 + t * 2);

    uint32_t* Cu = (uint32_t*)C;
    if (z < 2) {
        // per-head RMSNorm: warp's 64 cols = one head; reduce within quad only
#pragma unroll
        for (int mt = 0; mt < 4; mt++) {
            float s0 = 0.0f, s1 = 0.0f;
#pragma unroll
            for (int nt = 0; nt < 8; nt++) {
                float v0 = acc[mt][nt][0] + bb[nt].x;
                float v1 = acc[mt][nt][1] + bb[nt].y;
                float v2 = acc[mt][nt][2] + bb[nt].x;
                float v3 = acc[mt][nt][3] + bb[nt].y;
                s0 = fmaf(v0, v0, s0); s0 = fmaf(v1, v1, s0);
                s1 = fmaf(v2, v2, s1); s1 = fmaf(v3, v3, s1);
            }
            s0 += __shfl_xor_sync(0xffffffffu, s0, 1);
            s0 += __shfl_xor_sync(0xffffffffu, s0, 2);
            s1 += __shfl_xor_sync(0xffffffffu, s1, 1);
            s1 += __shfl_xor_sync(0xffffffffu, s1, 2);
            float sc0 = rsqrtf(s0 * (1.0f / 64.0f) + 1e-6f) * qsc;
            float sc1 = rsqrtf(s1 * (1.0f / 64.0f) + 1e-6f) * qsc;
            int r0 = bm + wm * 64 + mt * 16 + g;
#pragma unroll
            for (int nt = 0; nt < 8; nt++) {
                int cl = wn * 64 + nt * 8 + t * 2;
                float2 ww = *(const float2*)(normw + (cl & 63));
                float v0 = acc[mt][nt][0] + bb[nt].x;
                float v1 = acc[mt][nt][1] + bb[nt].y;
                float v2 = acc[mt][nt][2] + bb[nt].x;
                float v3 = acc[mt][nt][3] + bb[nt].y;
                uint2 o0 = {f2tf32(v0 * sc0 * ww.x), f2tf32(v1 * sc0 * ww.y)};
                uint2 o1 = {f2tf32(v2 * sc1 * ww.x), f2tf32(v3 * sc1 * ww.y)};
                *(uint2*)(Cu + (size_t)r0 * CD + bn + cl)       = o0;
                *(uint2*)(Cu + (size_t)(r0 + 8) * CD + bn + cl) = o1;
            }
        }
    } else {
        // V: store TRANSPOSED tf32 bits: vt[((b*16+h)*64+hd)*512 + n]
#pragma unroll
        for (int mt = 0; mt < 4; mt++) {
            int m0 = bm + wm * 64 + mt * 16 + g;
#pragma unroll
            for (int nt = 0; nt < 8; nt++) {
                int d0 = bn + wn * 64 + nt * 8 + t * 2;
                float v00 = acc[mt][nt][0] + bb[nt].x;
                float v01 = acc[mt][nt][1] + bb[nt].y;
                float v10 = acc[mt][nt][2] + bb[nt].x;
                float v11 = acc[mt][nt][3] + bb[nt].y;
                size_t ib = ((size_t)((m0 >> 9) * CH + (d0 >> 6)) * CHD + (d0 & 63)) * CN
                          + (m0 & 511);
                Cu[ib]            = f2tf32(v00);
                Cu[ib + CN]       = f2tf32(v01);
                Cu[ib + 8]        = f2tf32(v10);
                Cu[ib + CN + 8]   = f2tf32(v11);
            }
        }
    }
}

// ---------------------------------------------------------------------------
// final GEMM: out = (gate*o) @ Wo + bo, 4 warps x 64x64 warp tiles
// ---------------------------------------------------------------------------
__global__ __launch_bounds__(128, 2) void gemm_o(
    const uint32_t* __restrict__ A, const uint32_t* __restrict__ W,
    const float* __restrict__ bias, float* __restrict__ C)
{
    extern __shared__ uint32_t sm[];
    const int tid  = threadIdx.x;
    const int lane = tid & 31;
    const int warp = tid >> 5;
    const int wm   = warp >> 1;
    const int wn   = warp & 1;
    const int bm   = blockIdx.y * 128;
    const int bn   = blockIdx.x * 128;
    const int g    = lane >> 2;
    const int t    = lane & 3;
    const int lrow = lane & 7;
    const int lmat = lane >> 3;
    const uint32_t sb = (uint32_t)__cvta_generic_to_shared(sm);
    const int a_loff = ((lmat & 1) * 8 + lrow) * APAD + (lmat >> 1) * 4;
    const int b_loff = ((lmat >> 1) * 8 + lrow) * APAD + (lmat & 1) * 4;

    float acc[4][8][4];
#pragma unroll
    for (int i = 0; i < 4; i++)
#pragma unroll
        for (int j = 0; j < 8; j++)
#pragma unroll
            for (int r = 0; r < 4; r++) acc[i][j][r] = 0.0f;

    auto load_stage = [&](int kt, int st) {
        uint32_t as = sb + (uint32_t)(st * GA_STAGE) * 4u;
        uint32_t bs = as + GA_AW * 4u;
#pragma unroll
        for (int p = 0; p < 8; p++) {
            int idx = p * 128 + tid;
            int r = idx >> 3, c4 = (idx & 7) << 2;
            cp16(as + (uint32_t)(r * APAD + c4) * 4u,
                 A + (size_t)(bm + r) * CD + kt + c4);
            cp16(bs + (uint32_t)(r * APAD + c4) * 4u,
                 W + (size_t)(bn + r) * CD + kt + c4);
        }
        CP_COMMIT();
    };

    load_stage(0, 0);
    int st = 0;
    for (int it = 0; it < 32; it++) {
        CP_WAIT0();
        __syncthreads();
        if (it < 31) load_stage((it + 1) * 32, st ^ 1);
        const uint32_t as_b = sb + (uint32_t)(st * GA_STAGE) * 4u;
        const uint32_t bs_b = as_b + GA_AW * 4u;
#pragma unroll
        for (int ks = 0; ks < 4; ks++) {
            const int kc = ks * 8;
            uint32_t af[4][4], bq4[4][4];
#pragma unroll
            for (int mt = 0; mt < 4; mt++)
                ldsm_x4(af[mt], as_b + (uint32_t)((wm * 64 + mt * 16) * APAD + kc + a_loff) * 4u);
#pragma unroll
            for (int h2 = 0; h2 < 4; h2++)
                ldsm_x4(bq4[h2], bs_b + (uint32_t)((wn * 64 + h2 * 16) * APAD + kc + b_loff) * 4u);
#pragma unroll
            for (int mt = 0; mt < 4; mt++)
#pragma unroll
                for (int nt = 0; nt < 8; nt++)
                    mma_tf32(acc[mt][nt], af[mt], &bq4[nt >> 1][(nt & 1) * 2]);
        }
        st ^= 1;
    }

    float2 bb[8];
#pragma unroll
    for (int nt = 0; nt < 8; nt++)
        bb[nt] = *(const float2*)(bias + bn + wn * 64 + nt * 8 + t * 2);

#pragma unroll
    for (int mt = 0; mt < 4; mt++) {
        int r0 = bm + wm * 64 + mt * 16 + g;
        float ga0 = 1.0f + g_gacc[r0]     * (1.0f / 512.0f);
        float ga1 = 1.0f + g_gacc[r0 + 8] * (1.0f / 512.0f);
#pragma unroll
        for (int nt = 0; nt < 8; nt++) {
            int col = bn + wn * 64 + nt * 8 + t * 2;
            float2 w0 = {acc[mt][nt][0] * ga0 + bb[nt].x, acc[mt][nt][1] * ga0 + bb[nt].y};
            float2 w1 = {acc[mt][nt][2] * ga1 + bb[nt].x, acc[mt][nt][3] * ga1 + bb[nt].y};
            *(float2*)(C + (size_t)r0 * CD + col)       = w0;
            *(float2*)(C + (size_t)(r0 + 8) * CD + col) = w1;
        }
    }
}

// ---------------------------------------------------------------------------
// tf32 flash attention: fixed-bound softmax + ldmatrix fragments.
// 4 warps x 32 q-rows (two m16 tiles per warp)  (R15-validated)
// ---------------------------------------------------------------------------
__global__ __launch_bounds__(128, 2) void attn_t(
    const uint32_t* __restrict__ q, const uint32_t* __restrict__ k,
    const uint32_t* __restrict__ vt, float* __restrict__ o)
{
    extern __shared__ uint32_t sm[];

    const int tid  = threadIdx.x;
    const int lane = tid & 31;
    const int warp = tid >> 5;
    const int g    = lane >> 2;
    const int t    = lane & 3;
    const int bq   = blockIdx.y;
    const int h    = blockIdx.z;
    const int n0   = blockIdx.x * 128;
    const int gb   = bq & ~3;
    const int qrow = n0 + warp * 32;
    const uint32_t sb = (uint32_t)__cvta_generic_to_shared(sm);

    uint32_t qf[2][8][4];
#pragma unroll
    for (int u = 0; u < 2; u++) {
        const uint32_t* qb = q + ((size_t)(bq * CN + qrow + u * 16)) * CD + h * CHD;
#pragma unroll
        for (int ks = 0; ks < 8; ks++) {
            int c = ks * 8 + t;
            qf[u][ks][0] = qb[(size_t)g * CD + c];
            qf[u][ks][1] = qb[(size_t)(g + 8) * CD + c];
            qf[u][ks][2] = qb[(size_t)g * CD + c + 4];
            qf[u][ks][3] = qb[(size_t)(g + 8) * CD + c + 4];
        }
    }

    float oa[2][8][4];
#pragma unroll
    for (int u = 0; u < 2; u++)
#pragma unroll
        for (int nt = 0; nt < 8; nt++)
#pragma unroll
            for (int r = 0; r < 4; r++) oa[u][nt][r] = 0.0f;
    float li[2][2] = {{0.0f, 0.0f}, {0.0f, 0.0f}};

    uint32_t* Pw = sm + 2 * AT_STAGE + warp * 32 * PPAD;
    const uint32_t pw_sb = sb + (uint32_t)(2 * AT_STAGE + warp * 32 * PPAD) * 4u;
    const int lrow = lane & 7;
    const int lmat = lane >> 3;
    const uint32_t kv_off = (uint32_t)(lrow * KPAD + lmat * 4) * 4u;
    const uint32_t p_off = (uint32_t)(((lmat & 1) * 8 + lrow) * PPAD + (lmat >> 1) * 4) * 4u;

    auto load_kv = [&](int kc, int stg) {
        const int m0 = kc * 64;
        const int kb = gb + (m0 >> 9);
        const int kn = m0 & 511;
        uint32_t ksm = sb + (uint32_t)(stg * AT_STAGE) * 4u;
        uint32_t vsm = ksm + AT_KV * 4u;
#pragma unroll
        for (int p = 0; p < 8; p++) {
            int idx = p * 128 + tid;
            int r   = idx >> 4;
            int c4  = (idx & 15) << 2;
            uint32_t off = (uint32_t)(r * KPAD + c4) * 4u;
            cp16(ksm + off, k + ((size_t)(kb * CN + kn + r)) * CD + h * CHD + c4);
            cp16(vsm + off, vt + ((size_t)((kb * CH + h) * CHD + r)) * CN + kn + c4);
        }
        CP_COMMIT();
    };

    load_kv(0, 0);
    int st = 0;

    for (int kc = 0; kc < 32; kc++) {
        CP_WAIT0();
        __syncthreads();
        if (kc < 31) load_kv(kc + 1, st ^ 1);

        const uint32_t ks_sb = sb + (uint32_t)(st * AT_STAGE) * 4u;
        const uint32_t vs_sb = ks_sb + AT_KV * 4u;

        float sacc[2][8][4];
#pragma unroll
        for (int u = 0; u < 2; u++)
#pragma unroll
            for (int nt = 0; nt < 8; nt++)
#pragma unroll
                for (int r = 0; r < 4; r++) sacc[u][nt][r] = 0.0f;
#pragma unroll
        for (int nt = 0; nt < 8; nt++) {
            uint32_t rowa = ks_sb + (uint32_t)(nt * 8 * KPAD) * 4u + kv_off;
#pragma unroll
            for (int kp = 0; kp < 4; kp++) {
                uint32_t kb4[4];
                ldsm_x4(kb4, rowa + (uint32_t)(kp * 16) * 4u);
                mma_tf32(sacc[0][nt], qf[0][2 * kp],     kb4);
                mma_tf32(sacc[0][nt], qf[0][2 * kp + 1], kb4 + 2);
                mma_tf32(sacc[1][nt], qf[1][2 * kp],     kb4);
                mma_tf32(sacc[1][nt], qf[1][2 * kp + 1], kb4 + 2);
            }
        }

#pragma unroll
        for (int u = 0; u < 2; u++) {
#pragma unroll
            for (int nt = 0; nt < 8; nt++) {
                float p0 = __expf(sacc[u][nt][0] - SOFT_SHIFT);
                float p1 = __expf(sacc[u][nt][1] - SOFT_SHIFT);
                float p2 = __expf(sacc[u][nt][2] - SOFT_SHIFT);
                float p3 = __expf(sacc[u][nt][3] - SOFT_SHIFT);
                li[u][0] += p0 + p1;
                li[u][1] += p2 + p3;
                int col = nt * 8 + 2 * t;
                uint2 w0 = {f2tf32(p0), f2tf32(p1)};
                uint2 w1 = {f2tf32(p2), f2tf32(p3)};
                *(uint2*)&Pw[(u * 16 + g) * PPAD + col]       = w0;
                *(uint2*)&Pw[(u * 16 + g + 8) * PPAD + col]   = w1;
            }
        }
        __syncwarp();

        uint32_t pf[2][8][4];
#pragma unroll
        for (int u = 0; u < 2; u++)
#pragma unroll
            for (int ks = 0; ks < 8; ks++)
                ldsm_x4(pf[u][ks],
                        pw_sb + (uint32_t)(u * 16 * PPAD) * 4u + p_off + (uint32_t)(ks * 8) * 4u);

#pragma unroll
        for (int nt = 0; nt < 8; nt++) {
            uint32_t rowv = vs_sb + (uint32_t)(nt * 8 * KPAD) * 4u + kv_off;
#pragma unroll
            for (int kp = 0; kp < 4; kp++) {
                uint32_t vb4[4];
                ldsm_x4(vb4, rowv + (uint32_t)(kp * 16) * 4u);
                mma_tf32(oa[0][nt], pf[0][2 * kp],     vb4);
                mma_tf32(oa[0][nt], pf[0][2 * kp + 1], vb4 + 2);
                mma_tf32(oa[1][nt], pf[1][2 * kp],     vb4);
                mma_tf32(oa[1][nt], pf[1][2 * kp + 1], vb4 + 2);
            }
        }
        __syncwarp();
        st ^= 1;
    }

#pragma unroll
    for (int u = 0; u < 2; u++) {
        float l0 = li[u][0], l1 = li[u][1];
        l0 += __shfl_xor_sync(0xffffffffu, l0, 1);
        l0 += __shfl_xor_sync(0xffffffffu, l0, 2);
        l1 += __shfl_xor_sync(0xffffffffu, l1, 1);
        l1 += __shfl_xor_sync(0xffffffffu, l1, 2);
        float inv0 = 1.0f / l0, inv1 = 1.0f / l1;
        uint32_t* ob = (uint32_t*)(o + ((size_t)(bq * CN + qrow + u * 16)) * CD + h * CHD);
#pragma unroll
        for (int nt = 0; nt < 8; nt++) {
            int col = nt * 8 + 2 * t;
            uint2 r0 = {f2tf32(oa[u][nt][0] * inv0), f2tf32(oa[u][nt][1] * inv0)};
            uint2 r1 = {f2tf32(oa[u][nt][2] * inv1), f2tf32(oa[u][nt][3] * inv1)};
            *(uint2*)(ob + (size_t)g * CD + col)       = r0;
            *(uint2*)(ob + (size_t)(g + 8) * CD + col) = r1;
        }
    }
}

// ---------------------------------------------------------------------------
// launch
// ---------------------------------------------------------------------------
extern "C" void kernel_launch(void* const* d_in, const int* in_sizes, int n_in,
                              void* d_out, int out_size)
{
    (void)in_sizes; (void)n_in; (void)out_size;
    const float* x    = (const float*)d_in[0];
    const float* mask = (const float*)d_in[1];
    const float* Wq   = (const float*)d_in[2];
    const float* bq   = (const float*)d_in[3];
    const float* Wk   = (const float*)d_in[4];
    const float* bk   = (const float*)d_in[5];
    const float* Wv   = (const float*)d_in[6];
    const float* bv   = (const float*)d_in[7];
    const float* Wo   = (const float*)d_in[8];
    const float* bo   = (const float*)d_in[9];
    const float* Wiq  = (const float*)d_in[10];
    const float* biq  = (const float*)d_in[11];
    const float* Wik  = (const float*)d_in[12];
    const float* bik  = (const float*)d_in[13];
    const float* emb  = (const float*)d_in[14];
    const float* qw   = (const float*)d_in[15];
    const float* kw   = (const float*)d_in[16];
    float* out = (float*)d_out;

    float *qp, *kp, *vtp, *op;
    uint32_t *xt, *wq, *wk, *wv, *wo;
    cudaGetSymbolAddress((void**)&qp,  g_q);
    cudaGetSymbolAddress((void**)&kp,  g_k);
    cudaGetSymbolAddress((void**)&vtp, g_vt);
    cudaGetSymbolAddress((void**)&op,  g_o);
    cudaGetSymbolAddress((void**)&xt,  g_xt);
    cudaGetSymbolAddress((void**)&wq,  g_wq);
    cudaGetSymbolAddress((void**)&wk,  g_wk);
    cudaGetSymbolAddress((void**)&wv,  g_wv);
    cudaGetSymbolAddress((void**)&wo,  g_wo);

    static bool attr_done = false;
    if (!attr_done) {
        cudaFuncSetAttribute(gemm_qkv, cudaFuncAttributeMaxDynamicSharedMemorySize, SMEM_GEMM);
        cudaFuncSetAttribute(gemm_o,   cudaFuncAttributeMaxDynamicSharedMemorySize, SMEM_GEMM);
        cudaFuncSetAttribute(attn_t,   cudaFuncAttributeMaxDynamicSharedMemorySize, SMEM_ATTN);
        attr_done = true;
    }

    dim3 gemm_grid(8, 32);

    zero_e2_k<<<16, 256>>>();

    cvt_x_k<<<4096, 256>>>(x, xt);
    wtr_k<<<dim3(32, 32, 4), 256>>>(Wq, Wk, Wv, Wo, wq, wk, wv, wo);

    // instance-gate precompute (rank-5 factorization), off the critical tail
    e2_k<<<512, 256>>>(emb, Wik);
    prep_k<<<129, 256>>>(Wiq, biq, bik);

    gemm_qkv<<<dim3(8, 32, 3), 128, SMEM_GEMM>>>(xt, wq, wk, wv, bq, bk, bv,
                                                 qw, kw, qp, kp, vtp);

    attn_t<<<dim3(4, 8, 16), 128, SMEM_ATTN>>>((const uint32_t*)qp, (const uint32_t*)kp,
                                               (const uint32_t*)vtp, op);

    uvw_k<<<512, 256>>>(op);
    gate_k<<<512, 256>>>(mask);

    gemm_o<<<gemm_grid, 128, SMEM_GEMM>>>((const uint32_t*)op, wo, bo, out);
}